// round 3
// baseline (speedup 1.0000x reference)
#include <cuda_runtime.h>
#include <math.h>
#include <stdint.h>

#define NN 50000
#define CC 128
#define KK 32
#define BB 16
#define EPSF 1e-9f
#define TINYF 1.17549435e-38f

// ---------------- scratch (device globals: allocation-free) ----------------
struct Scratch {
  float avg_sum[KK];          // sum over n of s[n,k]
  float stpos[KK][2];         // sum s[n,k]*pos[n,d]
  float stpossq[KK];          // sum s[n,k]*|pos_n|^2
  float sum_s[BB][KK];        // per-segment sum of s
  float sum_s_pos[BB][KK][2]; // per-segment sum of s*pos
  float ent_sum;              // sum_n sum_k s*log(s+eps)
};
__device__ Scratch g_scr;
#define SCR_FLOATS 1665

__global__ void k_zero(float* __restrict__ out) {
  int i = blockIdx.x * 256 + threadIdx.x;
  if (i < BB*KK*CC) out[i] = 0.f;
  if (i < SCR_FLOATS) ((float*)&g_scr)[i] = 0.f;
}

// ---------------- JAX threefry2x32 (bit-exact) ----------------
__device__ __forceinline__ void tf_round(unsigned &x0, unsigned &x1, int r) {
  x0 += x1;
  x1 = __funnelshift_l(x1, x1, r);
  x1 ^= x0;
}
__device__ __forceinline__ uint2 threefry(unsigned k0, unsigned k1, unsigned x0, unsigned x1) {
  unsigned k2 = k0 ^ k1 ^ 0x1BD11BDAu;
  x0 += k0; x1 += k1;
  tf_round(x0,x1,13); tf_round(x0,x1,15); tf_round(x0,x1,26); tf_round(x0,x1,6);
  x0 += k1; x1 += k2 + 1u;
  tf_round(x0,x1,17); tf_round(x0,x1,29); tf_round(x0,x1,16); tf_round(x0,x1,24);
  x0 += k2; x1 += k0 + 2u;
  tf_round(x0,x1,13); tf_round(x0,x1,15); tf_round(x0,x1,26); tf_round(x0,x1,6);
  x0 += k0; x1 += k1 + 3u;
  tf_round(x0,x1,17); tf_round(x0,x1,29); tf_round(x0,x1,16); tf_round(x0,x1,24);
  x0 += k1; x1 += k2 + 4u;
  tf_round(x0,x1,13); tf_round(x0,x1,15); tf_round(x0,x1,26); tf_round(x0,x1,6);
  x0 += k2; x1 += k0 + 5u;
  return make_uint2(x0, x1);
}

// Partitionable counter-mode random bits (JAX default since ~0.4.36/0.5):
// bits(i) = o.x ^ o.y where o = threefry(key, (uint32(i>>32), uint32(i)))
__device__ __forceinline__ float gumbel_at(unsigned idx) {
  uint2 o = threefry(0u, 42u, 0u, idx);
  unsigned bits = o.x ^ o.y;
  float u = __uint_as_float((bits >> 9) | 0x3f800000u) - 1.0f;
  // uniform(minval=tiny): u*(1-tiny)+tiny then max(tiny, .): (1-tiny) rounds to 1
  u = fmaxf(TINYF, u + TINYF);
  return -logf(-logf(u));
}

// ---------------- fused assign kernel ----------------
// smem layout (floats):
#define SM_W2  0                  // 4096
#define SM_B1  4096               // 128
#define SM_B2  (4096+128)         // 32
#define SM_AM  (4096+160)         // 32
#define SM_UNI (4096+192)         // union: 8192  (stage1: xs[32*65]+w1s[32*128]; stage2: hs[64*128])
#define SM_LS  (SM_UNI+8192)      // 64*33 = 2112
#define SM_BSH (SM_LS+2112)       // 64 ints
#define SM_TOTAL_F (SM_BSH+64)    // 14656 floats = 58624 B

__global__ void __launch_bounds__(256, 2)
k_assign(const float* __restrict__ x, const float* __restrict__ pos,
         const float* __restrict__ W1, const float* __restrict__ b1,
         const float* __restrict__ W2, const float* __restrict__ b2,
         const float* __restrict__ scaling, const float* __restrict__ amask,
         const int* __restrict__ batch, float* __restrict__ out_s)
{
  extern __shared__ float sm[];
  float* W2s = sm + SM_W2;
  float* b1s = sm + SM_B1;
  float* b2s = sm + SM_B2;
  float* ams = sm + SM_AM;
  float* uni = sm + SM_UNI;
  float* xs  = uni;          // [32][65]
  float* w1s = uni + 2080;   // [32][128]
  float* hs  = uni;          // [64][128] (aliases stage-1 tiles)
  float* ls  = sm + SM_LS;   // [64][33]
  int*   bsh = (int*)(sm + SM_BSH);

  const int tid = threadIdx.x;
  const int tx  = tid & 31;
  const int wid = tid >> 5;
  const int r0  = blockIdx.x * 64;
  const int nvalid = min(64, NN - r0);

  for (int i = tid; i < CC*KK; i += 256) W2s[i] = W2[i];
  if (tid < 128) b1s[tid] = b1[tid];
  if (tid < 32)  { b2s[tid] = b2[tid]; ams[tid] = amask[tid]; }
  if (tid < 64)  bsh[tid] = (tid < nvalid) ? batch[r0 + tid] : 0;

  // ---- stage 1: h = relu(x @ W1 + b1), block tile 64x128, thread tile 8x4 ----
  float acc[8][4];
  #pragma unroll
  for (int i = 0; i < 8; i++) { acc[i][0]=0.f; acc[i][1]=0.f; acc[i][2]=0.f; acc[i][3]=0.f; }

  for (int c0 = 0; c0 < CC; c0 += 32) {
    __syncthreads();
    // x tile transposed: xs[c][r], pad 65 -> conflict-free stores/broadcast reads
    #pragma unroll
    for (int rr = 0; rr < 8; rr++) {
      int r = wid + rr*8;
      float v = (r < nvalid) ? x[(size_t)(r0 + r)*CC + c0 + tx] : 0.f;
      xs[tx*65 + r] = v;
    }
    // W1 tile [32][128] via float4 (coalesced)
    #pragma unroll
    for (int kk2 = 0; kk2 < 4; kk2++) {
      int k = wid + kk2*8;
      float4 v = *(const float4*)(W1 + (size_t)(c0 + k)*CC + tx*4);
      *(float4*)(w1s + k*CC + tx*4) = v;
    }
    __syncthreads();
    #pragma unroll
    for (int kc = 0; kc < 32; kc++) {
      float4 w = *(const float4*)(w1s + kc*CC + tx*4);
      #pragma unroll
      for (int rr = 0; rr < 8; rr++) {
        float xv = xs[kc*65 + wid*8 + rr];      // warp-uniform broadcast
        acc[rr][0] = fmaf(xv, w.x, acc[rr][0]);
        acc[rr][1] = fmaf(xv, w.y, acc[rr][1]);
        acc[rr][2] = fmaf(xv, w.z, acc[rr][2]);
        acc[rr][3] = fmaf(xv, w.w, acc[rr][3]);
      }
    }
  }
  __syncthreads();
  {
    float4 bb = *(const float4*)(b1s + tx*4);
    #pragma unroll
    for (int rr = 0; rr < 8; rr++) {
      float4 h;
      h.x = fmaxf(acc[rr][0] + bb.x, 0.f);
      h.y = fmaxf(acc[rr][1] + bb.y, 0.f);
      h.z = fmaxf(acc[rr][2] + bb.z, 0.f);
      h.w = fmaxf(acc[rr][3] + bb.w, 0.f);
      *(float4*)(hs + (wid*8 + rr)*CC + tx*4) = h;
    }
  }
  __syncthreads();

  // ---- stage 2: logits = (h @ W2 + b2) * scaling, masked ----
  const float sc = scaling[0];
  {
    float a[8];
    #pragma unroll
    for (int i = 0; i < 8; i++) a[i] = 0.f;
    for (int j = 0; j < CC; j += 4) {
      float w0 = W2s[(j+0)*KK + tx];
      float w1v = W2s[(j+1)*KK + tx];
      float w2v = W2s[(j+2)*KK + tx];
      float w3v = W2s[(j+3)*KK + tx];
      #pragma unroll
      for (int i = 0; i < 8; i++) {
        const float4 h4 = *(const float4*)(hs + (wid + 8*i)*CC + j);  // broadcast
        a[i] = fmaf(h4.x, w0,  a[i]);
        a[i] = fmaf(h4.y, w1v, a[i]);
        a[i] = fmaf(h4.z, w2v, a[i]);
        a[i] = fmaf(h4.w, w3v, a[i]);
      }
    }
    float am = ams[tx];
    float bv = b2s[tx];
    #pragma unroll
    for (int i = 0; i < 8; i++) {
      float v = (a[i] + bv) * sc;
      if (am == 0.f) v = -1e9f;
      ls[(wid + 8*i)*33 + tx] = v;
    }
  }
  __syncthreads();

  // ---- stage 3: gumbel + softmax + s write + reductions (warp per row, lane=k) ----
  float a_avg = 0.f, a_px = 0.f, a_py = 0.f, a_q = 0.f, a_ent = 0.f;
  int cur_b = -1; float b_s = 0.f, b_px = 0.f, b_py = 0.f;
  for (int r = wid; r < nvalid; r += 8) {
    const int grow = r0 + r;
    float z = ls[r*33 + tx];
    // exact JAX gumbel(key=42), partitionable counter-mode
    z += gumbel_at((unsigned)grow * 32u + (unsigned)tx);   // TAU = 1
    float m = z;
    #pragma unroll
    for (int off = 16; off; off >>= 1) m = fmaxf(m, __shfl_xor_sync(0xffffffffu, m, off));
    float e = expf(z - m);
    float ssum = e;
    #pragma unroll
    for (int off = 16; off; off >>= 1) ssum += __shfl_xor_sync(0xffffffffu, ssum, off);
    float s = e / ssum;
    out_s[(size_t)grow * KK + tx] = s;

    float px = pos[grow*2 + 0];
    float py = pos[grow*2 + 1];
    a_ent += s * logf(s + EPSF);
    a_avg += s;
    a_px = fmaf(s, px, a_px);
    a_py = fmaf(s, py, a_py);
    a_q  = fmaf(s, px*px + py*py, a_q);

    int b = bsh[r];   // warp-uniform; batch is sorted so b is nondecreasing
    if (b != cur_b) {
      if (cur_b >= 0) {
        atomicAdd(&g_scr.sum_s[cur_b][tx], b_s);
        atomicAdd(&g_scr.sum_s_pos[cur_b][tx][0], b_px);
        atomicAdd(&g_scr.sum_s_pos[cur_b][tx][1], b_py);
      }
      cur_b = b; b_s = 0.f; b_px = 0.f; b_py = 0.f;
    }
    b_s += s; b_px = fmaf(s, px, b_px); b_py = fmaf(s, py, b_py);
  }
  if (cur_b >= 0) {
    atomicAdd(&g_scr.sum_s[cur_b][tx], b_s);
    atomicAdd(&g_scr.sum_s_pos[cur_b][tx][0], b_px);
    atomicAdd(&g_scr.sum_s_pos[cur_b][tx][1], b_py);
    atomicAdd(&g_scr.avg_sum[tx], a_avg);
    atomicAdd(&g_scr.stpos[tx][0], a_px);
    atomicAdd(&g_scr.stpos[tx][1], a_py);
    atomicAdd(&g_scr.stpossq[tx], a_q);
    #pragma unroll
    for (int off = 16; off; off >>= 1) a_ent += __shfl_xor_sync(0xffffffffu, a_ent, off);
    if (tx == 0) atomicAdd(&g_scr.ent_sum, a_ent);
  }
}

// ---------------- pooled features: out[b] += S_b^T X_b (sorted-run chunks) ----------------
__global__ void __launch_bounds__(256)
k_pool(const float* __restrict__ x, const float* __restrict__ s,
       const int* __restrict__ batch, float* __restrict__ out)
{
  __shared__ float xs[32*128];
  __shared__ float ss[32*32];
  __shared__ int bsh[128];
  const int tid = threadIdx.x;
  const int r0 = blockIdx.x * 128;
  const int nvalid = min(128, NN - r0);
  if (tid < 128) bsh[tid] = (tid < nvalid) ? batch[r0 + tid] : -1;
  __syncthreads();
  const int c4 = tid & 31;   // owns cols 4*c4..4*c4+3
  const int kq = tid >> 5;   // owns k in {kq, kq+8, kq+16, kq+24}
  int p = 0;
  while (p < nvalid) {       // uniform control flow (shared bsh)
    const int b = bsh[p];
    int e = p + 1;
    while (e < nvalid && bsh[e] == b) e++;
    float acc[4][4];
    #pragma unroll
    for (int ki = 0; ki < 4; ki++) { acc[ki][0]=0.f; acc[ki][1]=0.f; acc[ki][2]=0.f; acc[ki][3]=0.f; }
    for (int t0 = p; t0 < e; t0 += 32) {
      const int tl = min(32, e - t0);
      __syncthreads();
      for (int idx = tid; idx < tl*32; idx += 256) {
        int r = idx >> 5, cq = idx & 31;
        *(float4*)(xs + r*128 + cq*4) = *(const float4*)(x + (size_t)(r0 + t0 + r)*128 + cq*4);
      }
      for (int idx = tid; idx < tl*8; idx += 256) {
        int r = idx >> 3, kq4 = idx & 7;
        *(float4*)(ss + r*32 + kq4*4) = *(const float4*)(s + (size_t)(r0 + t0 + r)*32 + kq4*4);
      }
      __syncthreads();
      for (int rr = 0; rr < tl; rr++) {
        float4 xv = *(const float4*)(xs + rr*128 + c4*4);
        #pragma unroll
        for (int ki = 0; ki < 4; ki++) {
          float sv = ss[rr*32 + kq + 8*ki];     // broadcast within warp
          acc[ki][0] = fmaf(sv, xv.x, acc[ki][0]);
          acc[ki][1] = fmaf(sv, xv.y, acc[ki][1]);
          acc[ki][2] = fmaf(sv, xv.z, acc[ki][2]);
          acc[ki][3] = fmaf(sv, xv.w, acc[ki][3]);
        }
      }
    }
    float* ob = out + (size_t)b * KK * CC;
    #pragma unroll
    for (int ki = 0; ki < 4; ki++) {
      float* dst = ob + (size_t)(kq + 8*ki)*CC + c4*4;
      atomicAdd(dst+0, acc[ki][0]);
      atomicAdd(dst+1, acc[ki][1]);
      atomicAdd(dst+2, acc[ki][2]);
      atomicAdd(dst+3, acc[ki][3]);
    }
    p = e;
  }
}

// ---------------- finisher: super_node_mu + 9 losses ----------------
__global__ void k_final(const float* __restrict__ amask, float* __restrict__ out)
{
  __shared__ float mu[BB*KK*2];
  __shared__ float wsum[16];
  float* out_mu = out + (size_t)BB*KK*CC + (size_t)NN*KK;
  float* out_losses = out_mu + BB*KK*2;
  const int tid = threadIdx.x;  // 512 threads
  if (tid < BB*KK) {
    int b = tid >> 5, k = tid & 31;
    float ssv = g_scr.sum_s[b][k] + EPSF;
    float mx = g_scr.sum_s_pos[b][k][0] / ssv;
    float my = g_scr.sum_s_pos[b][k][1] / ssv;
    mu[tid*2+0] = mx; mu[tid*2+1] = my;
    out_mu[tid*2+0] = mx; out_mu[tid*2+1] = my;
  }
  __syncthreads();
  float rep = 0.f;
  for (int idx = tid; idx < BB*KK*KK; idx += 512) {
    int b = idx >> 10, k1 = (idx >> 5) & 31, k2 = idx & 31;
    if (k1 != k2) {
      float dx = mu[(b*32+k1)*2+0] - mu[(b*32+k2)*2+0];
      float dy = mu[(b*32+k1)*2+1] - mu[(b*32+k2)*2+1];
      rep += 1.f / (dx*dx + dy*dy + 1.f);
    }
  }
  #pragma unroll
  for (int off = 16; off; off >>= 1) rep += __shfl_xor_sync(0xffffffffu, rep, off);
  if ((tid & 31) == 0) wsum[tid >> 5] = rep;
  __syncthreads();
  if (tid == 0) {
    float sep = 0.f;
    for (int i = 0; i < 16; i++) sep += wsum[i];
    sep /= ((float)(KK*(KK-1)) + EPSF);
    const float Nf = (float)NN;
    float avg[KK];
    float div = 0.f, bal = 0.f, prune = 0.f, am_sum = 0.f, mean = 0.f, mx = -1e30f;
    for (int k = 0; k < KK; k++) {
      avg[k] = g_scr.avg_sum[k] / Nf;
      div  += avg[k] * logf(avg[k] + EPSF);
      bal  += (1.f/32.f) * logf((1.f/32.f) / (avg[k] + EPSF));
      float amk = amask[k];
      prune += fabsf(avg[k] * (1.f - amk));
      am_sum += amk;
      mean += avg[k];
      mx = fmaxf(mx, avg[k]);
    }
    prune /= 32.f;
    mean  /= 32.f;
    float var = 0.f;
    for (int k = 0; k < KK; k++) { float d = avg[k] - mean; var += d*d; }
    var /= 31.f;
    float entropy = -g_scr.ent_sum / Nf;
    float maxp = fmaxf(mx - 0.8f, 0.f); maxp = maxp*maxp*10.f;
    float ent_avg = -div;
    float ep = fmaxf(0.5f*logf(32.f) - ent_avg, 0.f); ep = ep*ep;
    float collapse = (var + maxp + ep) * 2.0f;
    float sparsity = am_sum / 32.f * 0.01f;
    float spatial = 0.f;
    for (int k = 0; k < KK; k++) {
      float ssv = g_scr.avg_sum[k] + EPSF;
      float sx = g_scr.stpos[k][0] / ssv;
      float sy = g_scr.stpos[k][1] / ssv;
      float A  = g_scr.stpossq[k] / ssv;
      float musq = sx*sx + sy*sy;
      spatial += A - 2.f*musq + musq;
    }
    spatial /= 32.f;
    out_losses[0] = entropy;
    out_losses[1] = div;
    out_losses[2] = spatial;
    out_losses[3] = prune;
    out_losses[4] = sparsity;
    out_losses[5] = 0.f;
    out_losses[6] = collapse;
    out_losses[7] = bal;
    out_losses[8] = sep;
  }
}

// ---------------- launch ----------------
extern "C" void kernel_launch(void* const* d_in, const int* in_sizes, int n_in,
                              void* d_out, int out_size) {
  const float* x       = (const float*)d_in[0];
  const float* pos     = (const float*)d_in[1];
  const float* W1      = (const float*)d_in[2];
  const float* b1      = (const float*)d_in[3];
  const float* W2      = (const float*)d_in[4];
  const float* b2      = (const float*)d_in[5];
  const float* scaling = (const float*)d_in[6];
  const float* amask   = (const float*)d_in[7];
  const int*   batch   = (const int*)d_in[8];
  float* out   = (float*)d_out;
  float* out_s = out + BB*KK*CC;

  cudaFuncSetAttribute(k_assign, cudaFuncAttributeMaxDynamicSharedMemorySize, SM_TOTAL_F*4);

  k_zero<<<(BB*KK*CC + 255)/256, 256>>>(out);
  k_assign<<<(NN + 63)/64, 256, SM_TOTAL_F*4>>>(x, pos, W1, b1, W2, b2, scaling, amask, batch, out_s);
  k_pool<<<(NN + 127)/128, 256>>>(x, out_s, batch, out);
  k_final<<<1, 512>>>(amask, out);
}

// round 4
// speedup vs baseline: 1.0840x; 1.0840x over previous
#include <cuda_runtime.h>
#include <math.h>
#include <stdint.h>

#define NN 50000
#define CC 128
#define KK 32
#define BB 16
#define EPSF 1e-9f
#define TINYF 1.17549435e-38f

// ---------------- scratch (device globals: allocation-free) ----------------
struct Scratch {
  float avg_sum[KK];          // sum over n of s[n,k]
  float stpos[KK][2];         // sum s[n,k]*pos[n,d]
  float stpossq[KK];          // sum s[n,k]*|pos_n|^2
  float sum_s[BB][KK];        // per-segment sum of s
  float sum_s_pos[BB][KK][2]; // per-segment sum of s*pos
  float ent_sum;              // sum_n sum_k s*log(s+eps)
};
__device__ Scratch g_scr;
#define SCR_FLOATS 1665

__global__ void k_zero(float* __restrict__ out) {
  int i = blockIdx.x * 256 + threadIdx.x;
  if (i < BB*KK*CC) out[i] = 0.f;
  if (i < SCR_FLOATS) ((float*)&g_scr)[i] = 0.f;
}

// ---------------- JAX threefry2x32 (bit-exact) ----------------
__device__ __forceinline__ void tf_round(unsigned &x0, unsigned &x1, int r) {
  x0 += x1;
  x1 = __funnelshift_l(x1, x1, r);
  x1 ^= x0;
}
__device__ __forceinline__ uint2 threefry(unsigned k0, unsigned k1, unsigned x0, unsigned x1) {
  unsigned k2 = k0 ^ k1 ^ 0x1BD11BDAu;
  x0 += k0; x1 += k1;
  tf_round(x0,x1,13); tf_round(x0,x1,15); tf_round(x0,x1,26); tf_round(x0,x1,6);
  x0 += k1; x1 += k2 + 1u;
  tf_round(x0,x1,17); tf_round(x0,x1,29); tf_round(x0,x1,16); tf_round(x0,x1,24);
  x0 += k2; x1 += k0 + 2u;
  tf_round(x0,x1,13); tf_round(x0,x1,15); tf_round(x0,x1,26); tf_round(x0,x1,6);
  x0 += k0; x1 += k1 + 3u;
  tf_round(x0,x1,17); tf_round(x0,x1,29); tf_round(x0,x1,16); tf_round(x0,x1,24);
  x0 += k1; x1 += k2 + 4u;
  tf_round(x0,x1,13); tf_round(x0,x1,15); tf_round(x0,x1,26); tf_round(x0,x1,6);
  x0 += k2; x1 += k0 + 5u;
  return make_uint2(x0, x1);
}

// Partitionable counter-mode random bits (verified R3): bits(i) = o.x ^ o.y
__device__ __forceinline__ float gumbel_at(unsigned idx) {
  uint2 o = threefry(0u, 42u, 0u, idx);
  unsigned bits = o.x ^ o.y;
  float u = __uint_as_float((bits >> 9) | 0x3f800000u) - 1.0f;
  u = fmaxf(TINYF, u + TINYF);
  return -logf(-logf(u));
}

// ---------------- fused assign+pool kernel ----------------
// smem layout (floats):
#define SM_W2  0                  // 4096
#define SM_B1  4096               // 128
#define SM_B2  (4096+128)         // 32
#define SM_AM  (4096+160)         // 32
#define SM_UNI (4096+192)         // union: 8192 (stage1: xs[32*65]+w1s[32*128]; stage2: hs[64*128]; pool: x tile)
#define SM_LS  (SM_UNI+8192)      // 64*33 = 2112 (stage2: logits; pool: s)
#define SM_BSH (SM_LS+2112)       // 64 ints
#define SM_TOTAL_F (SM_BSH+64)    // 14656 floats = 58624 B

__global__ void __launch_bounds__(256, 2)
k_assign(const float* __restrict__ x, const float* __restrict__ pos,
         const float* __restrict__ W1, const float* __restrict__ b1,
         const float* __restrict__ W2, const float* __restrict__ b2,
         const float* __restrict__ scaling, const float* __restrict__ amask,
         const int* __restrict__ batch, float* __restrict__ out_s,
         float* __restrict__ out_pool)
{
  extern __shared__ float sm[];
  float* W2s = sm + SM_W2;
  float* b1s = sm + SM_B1;
  float* b2s = sm + SM_B2;
  float* ams = sm + SM_AM;
  float* uni = sm + SM_UNI;
  float* xs  = uni;          // [32][65]
  float* w1s = uni + 2080;   // [32][128]
  float* hs  = uni;          // [64][128] (aliases stage-1 tiles; pool: x tile)
  float* ls  = sm + SM_LS;   // [64][33]  (logits, then s)
  int*   bsh = (int*)(sm + SM_BSH);

  const int tid = threadIdx.x;
  const int tx  = tid & 31;
  const int wid = tid >> 5;
  const int r0  = blockIdx.x * 64;
  const int nvalid = min(64, NN - r0);

  for (int i = tid; i < CC*KK; i += 256) W2s[i] = W2[i];
  if (tid < 128) b1s[tid] = b1[tid];
  if (tid < 32)  { b2s[tid] = b2[tid]; ams[tid] = amask[tid]; }
  if (tid < 64)  bsh[tid] = (tid < nvalid) ? batch[r0 + tid] : 0;

  // ---- stage 1: h = relu(x @ W1 + b1), block tile 64x128, thread tile 8x4 ----
  float acc[8][4];
  #pragma unroll
  for (int i = 0; i < 8; i++) { acc[i][0]=0.f; acc[i][1]=0.f; acc[i][2]=0.f; acc[i][3]=0.f; }

  for (int c0 = 0; c0 < CC; c0 += 32) {
    __syncthreads();
    #pragma unroll
    for (int rr = 0; rr < 8; rr++) {
      int r = wid + rr*8;
      float v = (r < nvalid) ? x[(size_t)(r0 + r)*CC + c0 + tx] : 0.f;
      xs[tx*65 + r] = v;
    }
    #pragma unroll
    for (int kk2 = 0; kk2 < 4; kk2++) {
      int k = wid + kk2*8;
      float4 v = *(const float4*)(W1 + (size_t)(c0 + k)*CC + tx*4);
      *(float4*)(w1s + k*CC + tx*4) = v;
    }
    __syncthreads();
    #pragma unroll
    for (int kc = 0; kc < 32; kc++) {
      float4 w = *(const float4*)(w1s + kc*CC + tx*4);
      #pragma unroll
      for (int rr = 0; rr < 8; rr++) {
        float xv = xs[kc*65 + wid*8 + rr];
        acc[rr][0] = fmaf(xv, w.x, acc[rr][0]);
        acc[rr][1] = fmaf(xv, w.y, acc[rr][1]);
        acc[rr][2] = fmaf(xv, w.z, acc[rr][2]);
        acc[rr][3] = fmaf(xv, w.w, acc[rr][3]);
      }
    }
  }
  __syncthreads();
  {
    float4 bb = *(const float4*)(b1s + tx*4);
    #pragma unroll
    for (int rr = 0; rr < 8; rr++) {
      float4 h;
      h.x = fmaxf(acc[rr][0] + bb.x, 0.f);
      h.y = fmaxf(acc[rr][1] + bb.y, 0.f);
      h.z = fmaxf(acc[rr][2] + bb.z, 0.f);
      h.w = fmaxf(acc[rr][3] + bb.w, 0.f);
      *(float4*)(hs + (wid*8 + rr)*CC + tx*4) = h;
    }
  }
  __syncthreads();

  // ---- stage 2: logits = (h @ W2 + b2) * scaling, masked ----
  const float sc = scaling[0];
  {
    float a[8];
    #pragma unroll
    for (int i = 0; i < 8; i++) a[i] = 0.f;
    for (int j = 0; j < CC; j += 4) {
      float w0 = W2s[(j+0)*KK + tx];
      float w1v = W2s[(j+1)*KK + tx];
      float w2v = W2s[(j+2)*KK + tx];
      float w3v = W2s[(j+3)*KK + tx];
      #pragma unroll
      for (int i = 0; i < 8; i++) {
        const float4 h4 = *(const float4*)(hs + (wid + 8*i)*CC + j);
        a[i] = fmaf(h4.x, w0,  a[i]);
        a[i] = fmaf(h4.y, w1v, a[i]);
        a[i] = fmaf(h4.z, w2v, a[i]);
        a[i] = fmaf(h4.w, w3v, a[i]);
      }
    }
    float am = ams[tx];
    float bv = b2s[tx];
    #pragma unroll
    for (int i = 0; i < 8; i++) {
      float v = (a[i] + bv) * sc;
      if (am == 0.f) v = -1e9f;
      ls[(wid + 8*i)*33 + tx] = v;
    }
  }
  __syncthreads();

  // ---- stage 3: gumbel + softmax + s (to gmem AND smem) + reductions ----
  float a_avg = 0.f, a_px = 0.f, a_py = 0.f, a_q = 0.f, a_ent = 0.f;
  int cur_b = -1; float b_s = 0.f, b_px = 0.f, b_py = 0.f;
  for (int r = wid; r < nvalid; r += 8) {
    const int grow = r0 + r;
    float z = ls[r*33 + tx];
    z += gumbel_at((unsigned)grow * 32u + (unsigned)tx);   // TAU = 1
    float m = z;
    #pragma unroll
    for (int off = 16; off; off >>= 1) m = fmaxf(m, __shfl_xor_sync(0xffffffffu, m, off));
    float e = expf(z - m);
    float ssum = e;
    #pragma unroll
    for (int off = 16; off; off >>= 1) ssum += __shfl_xor_sync(0xffffffffu, ssum, off);
    float s = e / ssum;
    out_s[(size_t)grow * KK + tx] = s;
    ls[r*33 + tx] = s;                       // keep s in smem for pooling

    float px = pos[grow*2 + 0];
    float py = pos[grow*2 + 1];
    a_ent += s * logf(s + EPSF);
    a_avg += s;
    a_px = fmaf(s, px, a_px);
    a_py = fmaf(s, py, a_py);
    a_q  = fmaf(s, px*px + py*py, a_q);

    int b = bsh[r];
    if (b != cur_b) {
      if (cur_b >= 0) {
        atomicAdd(&g_scr.sum_s[cur_b][tx], b_s);
        atomicAdd(&g_scr.sum_s_pos[cur_b][tx][0], b_px);
        atomicAdd(&g_scr.sum_s_pos[cur_b][tx][1], b_py);
      }
      cur_b = b; b_s = 0.f; b_px = 0.f; b_py = 0.f;
    }
    b_s += s; b_px = fmaf(s, px, b_px); b_py = fmaf(s, py, b_py);
  }
  if (cur_b >= 0) {
    atomicAdd(&g_scr.sum_s[cur_b][tx], b_s);
    atomicAdd(&g_scr.sum_s_pos[cur_b][tx][0], b_px);
    atomicAdd(&g_scr.sum_s_pos[cur_b][tx][1], b_py);
    atomicAdd(&g_scr.avg_sum[tx], a_avg);
    atomicAdd(&g_scr.stpos[tx][0], a_px);
    atomicAdd(&g_scr.stpos[tx][1], a_py);
    atomicAdd(&g_scr.stpossq[tx], a_q);
    #pragma unroll
    for (int off = 16; off; off >>= 1) a_ent += __shfl_xor_sync(0xffffffffu, a_ent, off);
    if (tx == 0) atomicAdd(&g_scr.ent_sum, a_ent);
  }

  // ---- stage 4 (fused pooling): out[b] += S_tile^T X_tile ----
  // reload x tile into hs (h is dead; x is L2-resident from stage 1)
  for (int idx = tid; idx < nvalid*32; idx += 256) {
    int r = idx >> 5, cq = idx & 31;
    *(float4*)(hs + r*128 + cq*4) = *(const float4*)(x + (size_t)(r0 + r)*CC + cq*4);
  }
  __syncthreads();   // orders s-writes to ls and x-loads to hs vs reads below

  {
    const int c4 = tx;   // cols 4*tx..4*tx+3
    const int kq = wid;  // k in {wid, wid+8, wid+16, wid+24}
    int p = 0;
    while (p < nvalid) {           // uniform (shared bsh)
      const int b = bsh[p];
      int e = p + 1;
      while (e < nvalid && bsh[e] == b) e++;
      float pa[4][4];
      #pragma unroll
      for (int ki = 0; ki < 4; ki++) { pa[ki][0]=0.f; pa[ki][1]=0.f; pa[ki][2]=0.f; pa[ki][3]=0.f; }
      for (int r = p; r < e; r++) {
        float4 xv = *(const float4*)(hs + r*128 + c4*4);
        #pragma unroll
        for (int ki = 0; ki < 4; ki++) {
          float sv = ls[r*33 + kq + 8*ki];    // warp-uniform broadcast
          pa[ki][0] = fmaf(sv, xv.x, pa[ki][0]);
          pa[ki][1] = fmaf(sv, xv.y, pa[ki][1]);
          pa[ki][2] = fmaf(sv, xv.z, pa[ki][2]);
          pa[ki][3] = fmaf(sv, xv.w, pa[ki][3]);
        }
      }
      float* ob = out_pool + (size_t)b * KK * CC;
      #pragma unroll
      for (int ki = 0; ki < 4; ki++) {
        float* dst = ob + (size_t)(kq + 8*ki)*CC + c4*4;
        atomicAdd(dst+0, pa[ki][0]);
        atomicAdd(dst+1, pa[ki][1]);
        atomicAdd(dst+2, pa[ki][2]);
        atomicAdd(dst+3, pa[ki][3]);
      }
      p = e;
    }
  }
}

// ---------------- finisher: super_node_mu + 9 losses (parallelized) ----------------
__global__ void k_final(const float* __restrict__ amask, float* __restrict__ out)
{
  __shared__ float mu[BB*KK*2];
  __shared__ float wsum[16];
  __shared__ float s_sep;
  float* out_mu = out + (size_t)BB*KK*CC + (size_t)NN*KK;
  float* out_losses = out_mu + BB*KK*2;
  const int tid = threadIdx.x;  // 512 threads
  if (tid < BB*KK) {
    int b = tid >> 5, k = tid & 31;
    float ssv = g_scr.sum_s[b][k] + EPSF;
    float mx = g_scr.sum_s_pos[b][k][0] / ssv;
    float my = g_scr.sum_s_pos[b][k][1] / ssv;
    mu[tid*2+0] = mx; mu[tid*2+1] = my;
    out_mu[tid*2+0] = mx; out_mu[tid*2+1] = my;
  }
  __syncthreads();
  float rep = 0.f;
  for (int idx = tid; idx < BB*KK*KK; idx += 512) {
    int b = idx >> 10, k1 = (idx >> 5) & 31, k2 = idx & 31;
    if (k1 != k2) {
      float dx = mu[(b*32+k1)*2+0] - mu[(b*32+k2)*2+0];
      float dy = mu[(b*32+k1)*2+1] - mu[(b*32+k2)*2+1];
      rep += 1.f / (dx*dx + dy*dy + 1.f);
    }
  }
  #pragma unroll
  for (int off = 16; off; off >>= 1) rep += __shfl_xor_sync(0xffffffffu, rep, off);
  if ((tid & 31) == 0) wsum[tid >> 5] = rep;
  __syncthreads();
  if (tid == 0) {
    float sep = 0.f;
    for (int i = 0; i < 16; i++) sep += wsum[i];
    s_sep = sep / ((float)(KK*(KK-1)) + EPSF);
  }
  __syncthreads();

  // warp 0: per-k losses in parallel (lane = k)
  if (tid < 32) {
    const int k = tid;
    const float Nf = (float)NN;
    const float u = 1.f/32.f;
    float avg = g_scr.avg_sum[k] / Nf;
    float amk = amask[k];
    float div_k  = avg * logf(avg + EPSF);
    float bal_k  = u * logf(u / (avg + EPSF));
    float prn_k  = fabsf(avg * (1.f - amk));
    // spatial per k
    float ssv = g_scr.avg_sum[k] + EPSF;
    float sx = g_scr.stpos[k][0] / ssv;
    float sy = g_scr.stpos[k][1] / ssv;
    float A  = g_scr.stpossq[k] / ssv;
    float musq = sx*sx + sy*sy;
    float spa_k = A - 2.f*musq + musq;

    float div = div_k, bal = bal_k, prn = prn_k, spa = spa_k, ams = amk, mean = avg, mx = avg;
    #pragma unroll
    for (int off = 16; off; off >>= 1) {
      div  += __shfl_xor_sync(0xffffffffu, div,  off);
      bal  += __shfl_xor_sync(0xffffffffu, bal,  off);
      prn  += __shfl_xor_sync(0xffffffffu, prn,  off);
      spa  += __shfl_xor_sync(0xffffffffu, spa,  off);
      ams  += __shfl_xor_sync(0xffffffffu, ams,  off);
      mean += __shfl_xor_sync(0xffffffffu, mean, off);
      mx    = fmaxf(mx, __shfl_xor_sync(0xffffffffu, mx, off));
    }
    mean /= 32.f;
    float d = avg - mean;
    float var = d*d;
    #pragma unroll
    for (int off = 16; off; off >>= 1) var += __shfl_xor_sync(0xffffffffu, var, off);
    var /= 31.f;

    if (k == 0) {
      float entropy = -g_scr.ent_sum / Nf;
      float maxp = fmaxf(mx - 0.8f, 0.f); maxp = maxp*maxp*10.f;
      float ent_avg = -div;
      float ep = fmaxf(0.5f * 3.4657359027997265f - ent_avg, 0.f); ep = ep*ep;  // 0.5*log(32)
      float collapse = (var + maxp + ep) * 2.0f;
      out_losses[0] = entropy;
      out_losses[1] = div;
      out_losses[2] = spa / 32.f;
      out_losses[3] = prn / 32.f;
      out_losses[4] = ams / 32.f * 0.01f;
      out_losses[5] = 0.f;
      out_losses[6] = collapse;
      out_losses[7] = bal;
      out_losses[8] = s_sep;
    }
  }
}

// ---------------- launch ----------------
extern "C" void kernel_launch(void* const* d_in, const int* in_sizes, int n_in,
                              void* d_out, int out_size) {
  const float* x       = (const float*)d_in[0];
  const float* pos     = (const float*)d_in[1];
  const float* W1      = (const float*)d_in[2];
  const float* b1      = (const float*)d_in[3];
  const float* W2      = (const float*)d_in[4];
  const float* b2      = (const float*)d_in[5];
  const float* scaling = (const float*)d_in[6];
  const float* amask   = (const float*)d_in[7];
  const int*   batch   = (const int*)d_in[8];
  float* out   = (float*)d_out;
  float* out_s = out + BB*KK*CC;

  cudaFuncSetAttribute(k_assign, cudaFuncAttributeMaxDynamicSharedMemorySize, SM_TOTAL_F*4);

  k_zero<<<(BB*KK*CC + 255)/256, 256>>>(out);
  k_assign<<<(NN + 63)/64, 256, SM_TOTAL_F*4>>>(x, pos, W1, b1, W2, b2, scaling, amask, batch, out_s, out);
  k_final<<<1, 512>>>(amask, out);
}

// round 6
// speedup vs baseline: 1.1883x; 1.0963x over previous
#include <cuda_runtime.h>
#include <math.h>
#include <stdint.h>

#define NN 50000
#define CC 128
#define KK 32
#define BB 16
#define EPSF 1e-9f
#define TINYF 1.17549435e-38f

typedef unsigned long long u64;

// ---------------- f32x2 packed math (Blackwell, PTX-only) ----------------
__device__ __forceinline__ u64 pack2(float lo, float hi) {
  u64 r; asm("mov.b64 %0, {%1, %2};" : "=l"(r) : "f"(lo), "f"(hi)); return r;
}
__device__ __forceinline__ u64 dup2(float v) { return pack2(v, v); }
__device__ __forceinline__ void unpack2(u64 p, float& lo, float& hi) {
  asm("mov.b64 {%0, %1}, %2;" : "=f"(lo), "=f"(hi) : "l"(p));
}
__device__ __forceinline__ u64 ffma2(u64 a, u64 b, u64 c) {
  u64 d; asm("fma.rn.f32x2 %0, %1, %2, %3;" : "=l"(d) : "l"(a), "l"(b), "l"(c)); return d;
}

// ---------------- scratch (device globals: allocation-free) ----------------
struct Scratch {
  float avg_sum[KK];
  float stpos[KK][2];
  float stpossq[KK];
  float sum_s[BB][KK];
  float sum_s_pos[BB][KK][2];
  float ent_sum;
};
__device__ Scratch g_scr;
#define SCR_FLOATS 1665

__global__ void k_zero(float* __restrict__ out) {
  int i = blockIdx.x * 256 + threadIdx.x;
  if (i < BB*KK*CC) out[i] = 0.f;
  if (i < SCR_FLOATS) ((float*)&g_scr)[i] = 0.f;
}

// ---------------- JAX threefry2x32 (bit-exact) ----------------
__device__ __forceinline__ void tf_round(unsigned &x0, unsigned &x1, int r) {
  x0 += x1;
  x1 = __funnelshift_l(x1, x1, r);
  x1 ^= x0;
}
__device__ __forceinline__ uint2 threefry(unsigned k0, unsigned k1, unsigned x0, unsigned x1) {
  unsigned k2 = k0 ^ k1 ^ 0x1BD11BDAu;
  x0 += k0; x1 += k1;
  tf_round(x0,x1,13); tf_round(x0,x1,15); tf_round(x0,x1,26); tf_round(x0,x1,6);
  x0 += k1; x1 += k2 + 1u;
  tf_round(x0,x1,17); tf_round(x0,x1,29); tf_round(x0,x1,16); tf_round(x0,x1,24);
  x0 += k2; x1 += k0 + 2u;
  tf_round(x0,x1,13); tf_round(x0,x1,15); tf_round(x0,x1,26); tf_round(x0,x1,6);
  x0 += k0; x1 += k1 + 3u;
  tf_round(x0,x1,17); tf_round(x0,x1,29); tf_round(x0,x1,16); tf_round(x0,x1,24);
  x0 += k1; x1 += k2 + 4u;
  tf_round(x0,x1,13); tf_round(x0,x1,15); tf_round(x0,x1,26); tf_round(x0,x1,6);
  x0 += k2; x1 += k0 + 5u;
  return make_uint2(x0, x1);
}

// Partitionable counter-mode (verified R3): bits(i) = o.x ^ o.y
__device__ __forceinline__ float gumbel_at(unsigned idx) {
  uint2 o = threefry(0u, 42u, 0u, idx);
  unsigned bits = o.x ^ o.y;
  float u = __uint_as_float((bits >> 9) | 0x3f800000u) - 1.0f;
  u = fmaxf(TINYF, u + TINYF);
  return -__logf(-__logf(u));
}

// ---------------- fused assign+pool kernel ----------------
// smem layout (floats):
#define XS_STRIDE 66              // even stride: row-pairs are 8B-aligned for LDS.64
#define SM_W2  0                  // 4096
#define SM_B1  4096               // 128
#define SM_B2  (4096+128)         // 32
#define SM_AM  (4096+160)         // 32
#define SM_UNI (4096+192)         // union: 8192 (stage1: xs[32*66]+w1s[32*128]=6208; stage2/pool: hs[64*128])
#define SM_LS  (SM_UNI+8192)      // 64*33 = 2112 (logits, then s)
#define SM_BSH (SM_LS+2112)       // 64 ints
#define SM_TOTAL_F (SM_BSH+64)    // 14656 floats = 58624 B

__global__ void __launch_bounds__(256, 2)
k_assign(const float* __restrict__ x, const float* __restrict__ pos,
         const float* __restrict__ W1, const float* __restrict__ b1,
         const float* __restrict__ W2, const float* __restrict__ b2,
         const float* __restrict__ scaling, const float* __restrict__ amask,
         const int* __restrict__ batch, float* __restrict__ out_s,
         float* __restrict__ out_pool)
{
  extern __shared__ float sm[];
  float* W2s = sm + SM_W2;
  float* b1s = sm + SM_B1;
  float* b2s = sm + SM_B2;
  float* ams = sm + SM_AM;
  float* uni = sm + SM_UNI;
  float* xs  = uni;               // [32][66]
  float* w1s = uni + 32*XS_STRIDE;// [32][128]
  float* hs  = uni;               // [64][128] (aliases stage-1 tiles; pool: x tile)
  float* ls  = sm + SM_LS;        // [64][33]
  int*   bsh = (int*)(sm + SM_BSH);

  const int tid = threadIdx.x;
  const int tx  = tid & 31;
  const int wid = tid >> 5;
  const int r0  = blockIdx.x * 64;
  const int nvalid = min(64, NN - r0);

  for (int i = tid; i < CC*KK; i += 256) W2s[i] = W2[i];
  if (tid < 128) b1s[tid] = b1[tid];
  if (tid < 32)  { b2s[tid] = b2[tid]; ams[tid] = amask[tid]; }
  if (tid < 64)  bsh[tid] = (tid < nvalid) ? batch[r0 + tid] : 0;

  // ---- stage 1: h = relu(x @ W1 + b1), 64x128 tile, f32x2 packed over row pairs ----
  u64 acc2[4][4];
  #pragma unroll
  for (int p = 0; p < 4; p++) { acc2[p][0]=0ull; acc2[p][1]=0ull; acc2[p][2]=0ull; acc2[p][3]=0ull; }

  for (int c0 = 0; c0 < CC; c0 += 32) {
    __syncthreads();
    // x tile transposed: xs[c][r]  (2-way store conflict from even stride; cheap)
    #pragma unroll
    for (int rr = 0; rr < 8; rr++) {
      int r = wid + rr*8;
      float v = (r < nvalid) ? x[(size_t)(r0 + r)*CC + c0 + tx] : 0.f;
      xs[tx*XS_STRIDE + r] = v;
    }
    #pragma unroll
    for (int kk2 = 0; kk2 < 4; kk2++) {
      int k = wid + kk2*8;
      float4 v = *(const float4*)(W1 + (size_t)(c0 + k)*CC + tx*4);
      *(float4*)(w1s + k*CC + tx*4) = v;
    }
    __syncthreads();
    #pragma unroll
    for (int kc = 0; kc < 32; kc++) {
      float4 w = *(const float4*)(w1s + kc*CC + tx*4);
      u64 wx = dup2(w.x), wy = dup2(w.y), wz = dup2(w.z), ww = dup2(w.w);
      const u64* xp = (const u64*)(xs + kc*XS_STRIDE + wid*8);  // warp-uniform LDS.64
      #pragma unroll
      for (int p = 0; p < 4; p++) {
        u64 xv = xp[p];          // rows (wid*8+2p, wid*8+2p+1)
        acc2[p][0] = ffma2(xv, wx, acc2[p][0]);
        acc2[p][1] = ffma2(xv, wy, acc2[p][1]);
        acc2[p][2] = ffma2(xv, wz, acc2[p][2]);
        acc2[p][3] = ffma2(xv, ww, acc2[p][3]);
      }
    }
  }
  __syncthreads();
  {
    float4 bb = *(const float4*)(b1s + tx*4);
    #pragma unroll
    for (int p = 0; p < 4; p++) {
      float a0, a1;
      float4 h0, h1;
      unpack2(acc2[p][0], a0, a1); h0.x = fmaxf(a0 + bb.x, 0.f); h1.x = fmaxf(a1 + bb.x, 0.f);
      unpack2(acc2[p][1], a0, a1); h0.y = fmaxf(a0 + bb.y, 0.f); h1.y = fmaxf(a1 + bb.y, 0.f);
      unpack2(acc2[p][2], a0, a1); h0.z = fmaxf(a0 + bb.z, 0.f); h1.z = fmaxf(a1 + bb.z, 0.f);
      unpack2(acc2[p][3], a0, a1); h0.w = fmaxf(a0 + bb.w, 0.f); h1.w = fmaxf(a1 + bb.w, 0.f);
      *(float4*)(hs + (wid*8 + 2*p    )*CC + tx*4) = h0;
      *(float4*)(hs + (wid*8 + 2*p + 1)*CC + tx*4) = h1;
    }
  }
  __syncthreads();

  // ---- stage 2: logits = (h @ W2 + b2) * scaling, f32x2 packed over K ----
  const float sc = scaling[0];
  {
    u64 a2[8];
    #pragma unroll
    for (int i = 0; i < 8; i++) a2[i] = 0ull;
    for (int j = 0; j < CC; j += 4) {
      u64 wA = pack2(W2s[(j+0)*KK + tx], W2s[(j+1)*KK + tx]);
      u64 wB = pack2(W2s[(j+2)*KK + tx], W2s[(j+3)*KK + tx]);
      #pragma unroll
      for (int i = 0; i < 8; i++) {
        ulonglong2 h2 = *(const ulonglong2*)(hs + (wid + 8*i)*CC + j);  // broadcast LDS.128
        a2[i] = ffma2(h2.x, wA, a2[i]);
        a2[i] = ffma2(h2.y, wB, a2[i]);
      }
    }
    float am = ams[tx];
    float bv = b2s[tx];
    #pragma unroll
    for (int i = 0; i < 8; i++) {
      float e, o;
      unpack2(a2[i], e, o);
      float v = ((e + o) + bv) * sc;
      if (am == 0.f) v = -1e9f;
      ls[(wid + 8*i)*33 + tx] = v;
    }
  }
  __syncthreads();

  // ---- stage 3: gumbel + softmax + s (gmem AND smem) + reductions ----
  float a_avg = 0.f, a_px = 0.f, a_py = 0.f, a_q = 0.f, a_ent = 0.f;
  int cur_b = -1; float b_s = 0.f, b_px = 0.f, b_py = 0.f;
  for (int r = wid; r < nvalid; r += 8) {
    const int grow = r0 + r;
    float z = ls[r*33 + tx];
    z += gumbel_at((unsigned)grow * 32u + (unsigned)tx);   // TAU = 1
    float m = z;
    #pragma unroll
    for (int off = 16; off; off >>= 1) m = fmaxf(m, __shfl_xor_sync(0xffffffffu, m, off));
    float e = __expf(z - m);
    float ssum = e;
    #pragma unroll
    for (int off = 16; off; off >>= 1) ssum += __shfl_xor_sync(0xffffffffu, ssum, off);
    float s = e / ssum;
    out_s[(size_t)grow * KK + tx] = s;
    ls[r*33 + tx] = s;

    float px = pos[grow*2 + 0];
    float py = pos[grow*2 + 1];
    a_ent += s * __logf(s + EPSF);
    a_avg += s;
    a_px = fmaf(s, px, a_px);
    a_py = fmaf(s, py, a_py);
    a_q  = fmaf(s, px*px + py*py, a_q);

    int b = bsh[r];
    if (b != cur_b) {
      if (cur_b >= 0) {
        atomicAdd(&g_scr.sum_s[cur_b][tx], b_s);
        atomicAdd(&g_scr.sum_s_pos[cur_b][tx][0], b_px);
        atomicAdd(&g_scr.sum_s_pos[cur_b][tx][1], b_py);
      }
      cur_b = b; b_s = 0.f; b_px = 0.f; b_py = 0.f;
    }
    b_s += s; b_px = fmaf(s, px, b_px); b_py = fmaf(s, py, b_py);
  }
  if (cur_b >= 0) {
    atomicAdd(&g_scr.sum_s[cur_b][tx], b_s);
    atomicAdd(&g_scr.sum_s_pos[cur_b][tx][0], b_px);
    atomicAdd(&g_scr.sum_s_pos[cur_b][tx][1], b_py);
    atomicAdd(&g_scr.avg_sum[tx], a_avg);
    atomicAdd(&g_scr.stpos[tx][0], a_px);
    atomicAdd(&g_scr.stpos[tx][1], a_py);
    atomicAdd(&g_scr.stpossq[tx], a_q);
    #pragma unroll
    for (int off = 16; off; off >>= 1) a_ent += __shfl_xor_sync(0xffffffffu, a_ent, off);
    if (tx == 0) atomicAdd(&g_scr.ent_sum, a_ent);
  }

  // ---- stage 4 (fused pooling): out[b] += S_tile^T X_tile, f32x2 over col pairs ----
  for (int idx = tid; idx < nvalid*32; idx += 256) {
    int r = idx >> 5, cq = idx & 31;
    *(float4*)(hs + r*128 + cq*4) = *(const float4*)(x + (size_t)(r0 + r)*CC + cq*4);
  }
  __syncthreads();

  {
    int p = 0;
    while (p < nvalid) {           // uniform (shared bsh)
      const int b = bsh[p];
      int e = p + 1;
      while (e < nvalid && bsh[e] == b) e++;
      u64 pa2[4][2];
      #pragma unroll
      for (int ki = 0; ki < 4; ki++) { pa2[ki][0]=0ull; pa2[ki][1]=0ull; }
      for (int r = p; r < e; r++) {
        ulonglong2 x2 = *(const ulonglong2*)(hs + r*128 + tx*4);
        #pragma unroll
        for (int ki = 0; ki < 4; ki++) {
          u64 svp = dup2(ls[r*33 + wid + 8*ki]);   // warp-uniform broadcast
          pa2[ki][0] = ffma2(svp, x2.x, pa2[ki][0]);
          pa2[ki][1] = ffma2(svp, x2.y, pa2[ki][1]);
        }
      }
      float* ob = out_pool + (size_t)b * KK * CC;
      #pragma unroll
      for (int ki = 0; ki < 4; ki++) {
        float v0, v1, v2, v3;
        unpack2(pa2[ki][0], v0, v1);
        unpack2(pa2[ki][1], v2, v3);
        float* dst = ob + (size_t)(wid + 8*ki)*CC + tx*4;
        atomicAdd(dst+0, v0);
        atomicAdd(dst+1, v1);
        atomicAdd(dst+2, v2);
        atomicAdd(dst+3, v3);
      }
      p = e;
    }
  }
}

// ---------------- finisher: super_node_mu + 9 losses (parallelized) ----------------
__global__ void k_final(const float* __restrict__ amask, float* __restrict__ out)
{
  __shared__ float mu[BB*KK*2];
  __shared__ float wsum[16];
  __shared__ float s_sep;
  float* out_mu = out + (size_t)BB*KK*CC + (size_t)NN*KK;
  float* out_losses = out_mu + BB*KK*2;
  const int tid = threadIdx.x;  // 512 threads
  if (tid < BB*KK) {
    int b = tid >> 5, k = tid & 31;
    float ssv = g_scr.sum_s[b][k] + EPSF;
    float mx = g_scr.sum_s_pos[b][k][0] / ssv;
    float my = g_scr.sum_s_pos[b][k][1] / ssv;
    mu[tid*2+0] = mx; mu[tid*2+1] = my;
    out_mu[tid*2+0] = mx; out_mu[tid*2+1] = my;
  }
  __syncthreads();
  float rep = 0.f;
  for (int idx = tid; idx < BB*KK*KK; idx += 512) {
    int b = idx >> 10, k1 = (idx >> 5) & 31, k2 = idx & 31;
    if (k1 != k2) {
      float dx = mu[(b*32+k1)*2+0] - mu[(b*32+k2)*2+0];
      float dy = mu[(b*32+k1)*2+1] - mu[(b*32+k2)*2+1];
      rep += 1.f / (dx*dx + dy*dy + 1.f);
    }
  }
  #pragma unroll
  for (int off = 16; off; off >>= 1) rep += __shfl_xor_sync(0xffffffffu, rep, off);
  if ((tid & 31) == 0) wsum[tid >> 5] = rep;
  __syncthreads();
  if (tid == 0) {
    float sep = 0.f;
    for (int i = 0; i < 16; i++) sep += wsum[i];
    s_sep = sep / ((float)(KK*(KK-1)) + EPSF);
  }
  __syncthreads();

  if (tid < 32) {
    const int k = tid;
    const float Nf = (float)NN;
    const float u = 1.f/32.f;
    float avg = g_scr.avg_sum[k] / Nf;
    float amk = amask[k];
    float div_k  = avg * logf(avg + EPSF);
    float bal_k  = u * logf(u / (avg + EPSF));
    float prn_k  = fabsf(avg * (1.f - amk));
    float ssv = g_scr.avg_sum[k] + EPSF;
    float sx = g_scr.stpos[k][0] / ssv;
    float sy = g_scr.stpos[k][1] / ssv;
    float A  = g_scr.stpossq[k] / ssv;
    float musq = sx*sx + sy*sy;
    float spa_k = A - 2.f*musq + musq;

    float div = div_k, bal = bal_k, prn = prn_k, spa = spa_k, ams = amk, mean = avg, mx = avg;
    #pragma unroll
    for (int off = 16; off; off >>= 1) {
      div  += __shfl_xor_sync(0xffffffffu, div,  off);
      bal  += __shfl_xor_sync(0xffffffffu, bal,  off);
      prn  += __shfl_xor_sync(0xffffffffu, prn,  off);
      spa  += __shfl_xor_sync(0xffffffffu, spa,  off);
      ams  += __shfl_xor_sync(0xffffffffu, ams,  off);
      mean += __shfl_xor_sync(0xffffffffu, mean, off);
      mx    = fmaxf(mx, __shfl_xor_sync(0xffffffffu, mx, off));
    }
    mean /= 32.f;
    float d = avg - mean;
    float var = d*d;
    #pragma unroll
    for (int off = 16; off; off >>= 1) var += __shfl_xor_sync(0xffffffffu, var, off);
    var /= 31.f;

    if (k == 0) {
      float entropy = -g_scr.ent_sum / Nf;
      float maxp = fmaxf(mx - 0.8f, 0.f); maxp = maxp*maxp*10.f;
      float ent_avg = -div;
      float ep = fmaxf(0.5f * 3.4657359027997265f - ent_avg, 0.f); ep = ep*ep;
      float collapse = (var + maxp + ep) * 2.0f;
      out_losses[0] = entropy;
      out_losses[1] = div;
      out_losses[2] = spa / 32.f;
      out_losses[3] = prn / 32.f;
      out_losses[4] = ams / 32.f * 0.01f;
      out_losses[5] = 0.f;
      out_losses[6] = collapse;
      out_losses[7] = bal;
      out_losses[8] = s_sep;
    }
  }
}

// ---------------- launch ----------------
extern "C" void kernel_launch(void* const* d_in, const int* in_sizes, int n_in,
                              void* d_out, int out_size) {
  const float* x       = (const float*)d_in[0];
  const float* pos     = (const float*)d_in[1];
  const float* W1      = (const float*)d_in[2];
  const float* b1      = (const float*)d_in[3];
  const float* W2      = (const float*)d_in[4];
  const float* b2      = (const float*)d_in[5];
  const float* scaling = (const float*)d_in[6];
  const float* amask   = (const float*)d_in[7];
  const int*   batch   = (const int*)d_in[8];
  float* out   = (float*)d_out;
  float* out_s = out + BB*KK*CC;

  cudaFuncSetAttribute(k_assign, cudaFuncAttributeMaxDynamicSharedMemorySize, SM_TOTAL_F*4);

  k_zero<<<(BB*KK*CC + 255)/256, 256>>>(out);
  k_assign<<<(NN + 63)/64, 256, SM_TOTAL_F*4>>>(x, pos, W1, b1, W2, b2, scaling, amask, batch, out_s, out);
  k_final<<<1, 512>>>(amask, out);
}

// round 8
// speedup vs baseline: 1.3260x; 1.1158x over previous
#include <cuda_runtime.h>
#include <math.h>
#include <stdint.h>

#define NN 50000
#define CC 128
#define KK 32
#define BB 16
#define EPSF 1e-9f
#define TINYF 1.17549435e-38f

typedef unsigned long long u64;

// ---------------- f32x2 packed math (Blackwell, PTX-only) ----------------
__device__ __forceinline__ u64 pack2(float lo, float hi) {
  u64 r; asm("mov.b64 %0, {%1, %2};" : "=l"(r) : "f"(lo), "f"(hi)); return r;
}
__device__ __forceinline__ u64 dup2(float v) { return pack2(v, v); }
__device__ __forceinline__ void unpack2(u64 p, float& lo, float& hi) {
  asm("mov.b64 {%0, %1}, %2;" : "=f"(lo), "=f"(hi) : "l"(p));
}
__device__ __forceinline__ u64 ffma2(u64 a, u64 b, u64 c) {
  u64 d; asm("fma.rn.f32x2 %0, %1, %2, %3;" : "=l"(d) : "l"(a), "l"(b), "l"(c)); return d;
}

// ---------------- scratch (device globals: allocation-free) ----------------
struct Scratch {
  float avg_sum[KK];
  float stpos[KK][2];
  float stpossq[KK];
  float sum_s[BB][KK];
  float sum_s_pos[BB][KK][2];
  float ent_sum;
};
__device__ Scratch g_scr;
#define SCR_FLOATS 1665

__global__ void k_zero(float* __restrict__ out) {
  int i = blockIdx.x * 256 + threadIdx.x;
  float4 z = make_float4(0.f, 0.f, 0.f, 0.f);
  if (i < (BB*KK*CC)/4) ((float4*)out)[i] = z;
  if (i < SCR_FLOATS) ((float*)&g_scr)[i] = 0.f;
}

// ---------------- JAX threefry2x32 (bit-exact) ----------------
__device__ __forceinline__ void tf_round(unsigned &x0, unsigned &x1, int r) {
  x0 += x1;
  x1 = __funnelshift_l(x1, x1, r);
  x1 ^= x0;
}
__device__ __forceinline__ uint2 threefry(unsigned k0, unsigned k1, unsigned x0, unsigned x1) {
  unsigned k2 = k0 ^ k1 ^ 0x1BD11BDAu;
  x0 += k0; x1 += k1;
  tf_round(x0,x1,13); tf_round(x0,x1,15); tf_round(x0,x1,26); tf_round(x0,x1,6);
  x0 += k1; x1 += k2 + 1u;
  tf_round(x0,x1,17); tf_round(x0,x1,29); tf_round(x0,x1,16); tf_round(x0,x1,24);
  x0 += k2; x1 += k0 + 2u;
  tf_round(x0,x1,13); tf_round(x0,x1,15); tf_round(x0,x1,26); tf_round(x0,x1,6);
  x0 += k0; x1 += k1 + 3u;
  tf_round(x0,x1,17); tf_round(x0,x1,29); tf_round(x0,x1,16); tf_round(x0,x1,24);
  x0 += k1; x1 += k2 + 4u;
  tf_round(x0,x1,13); tf_round(x0,x1,15); tf_round(x0,x1,26); tf_round(x0,x1,6);
  x0 += k2; x1 += k0 + 5u;
  return make_uint2(x0, x1);
}

// Partitionable counter-mode (verified R3): bits(i) = o.x ^ o.y
__device__ __forceinline__ float gumbel_at(unsigned idx) {
  uint2 o = threefry(0u, 42u, 0u, idx);
  unsigned bits = o.x ^ o.y;
  float u = __uint_as_float((bits >> 9) | 0x3f800000u) - 1.0f;
  u = fmaxf(TINYF, u + TINYF);
  return -__logf(-__logf(u));
}

// ---------------- fused assign+pool kernel ----------------
// smem layout (floats):
#define XS_STRIDE 66              // even stride: row-pairs are 8B-aligned for LDS.64
#define SM_W2  0                  // 4096
#define SM_B1  4096               // 128
#define SM_B2  (4096+128)         // 32
#define SM_AM  (4096+160)         // 32
#define SM_UNI (4096+192)         // union: 8192 (stage1: xs[32*66]+w1s[32*128]=6208; stage2/pool: hs[64*128])
#define SM_LS  (SM_UNI+8192)      // 64*33 = 2112 (logits, then s)
#define SM_BSH (SM_LS+2112)       // 64 ints
#define SM_TOTAL_F (SM_BSH+64)    // 14656 floats = 58624 B

__global__ void __launch_bounds__(256, 3)
k_assign(const float* __restrict__ x, const float* __restrict__ pos,
         const float* __restrict__ W1, const float* __restrict__ b1,
         const float* __restrict__ W2, const float* __restrict__ b2,
         const float* __restrict__ scaling, const float* __restrict__ amask,
         const int* __restrict__ batch, float* __restrict__ out_s,
         float* __restrict__ out_pool)
{
  extern __shared__ float sm[];
  float* W2s = sm + SM_W2;
  float* b1s = sm + SM_B1;
  float* b2s = sm + SM_B2;
  float* ams = sm + SM_AM;
  float* uni = sm + SM_UNI;
  float* xs  = uni;               // [32][66]
  float* w1s = uni + 32*XS_STRIDE;// [32][128]
  float* hs  = uni;               // [64][128] (aliases stage-1 tiles; pool: x tile)
  float* ls  = sm + SM_LS;        // [64][33]
  int*   bsh = (int*)(sm + SM_BSH);

  const int tid = threadIdx.x;
  const int tx  = tid & 31;
  const int wid = tid >> 5;
  const int r0  = blockIdx.x * 64;
  const int nvalid = min(64, NN - r0);

  for (int i = tid; i < CC*KK; i += 256) W2s[i] = W2[i];
  if (tid < 128) b1s[tid] = b1[tid];
  if (tid < 32)  { b2s[tid] = b2[tid]; ams[tid] = amask[tid]; }
  if (tid < 64)  bsh[tid] = (tid < nvalid) ? batch[r0 + tid] : 0;

  // ---- stage 1: h = relu(x @ W1 + b1), 64x128 tile, f32x2 packed over row pairs ----
  u64 acc2[4][4];
  #pragma unroll
  for (int p = 0; p < 4; p++) { acc2[p][0]=0ull; acc2[p][1]=0ull; acc2[p][2]=0ull; acc2[p][3]=0ull; }

  for (int c0 = 0; c0 < CC; c0 += 32) {
    __syncthreads();
    // x tile transposed: xs[c][r]  (2-way store conflict from even stride; cheap)
    #pragma unroll
    for (int rr = 0; rr < 8; rr++) {
      int r = wid + rr*8;
      float v = (r < nvalid) ? x[(size_t)(r0 + r)*CC + c0 + tx] : 0.f;
      xs[tx*XS_STRIDE + r] = v;
    }
    #pragma unroll
    for (int kk2 = 0; kk2 < 4; kk2++) {
      int k = wid + kk2*8;
      float4 v = *(const float4*)(W1 + (size_t)(c0 + k)*CC + tx*4);
      *(float4*)(w1s + k*CC + tx*4) = v;
    }
    __syncthreads();
    #pragma unroll
    for (int kc = 0; kc < 32; kc++) {
      float4 w = *(const float4*)(w1s + kc*CC + tx*4);
      u64 wx = dup2(w.x), wy = dup2(w.y), wz = dup2(w.z), ww = dup2(w.w);
      const u64* xp = (const u64*)(xs + kc*XS_STRIDE + wid*8);  // warp-uniform LDS.64
      #pragma unroll
      for (int p = 0; p < 4; p++) {
        u64 xv = xp[p];          // rows (wid*8+2p, wid*8+2p+1)
        acc2[p][0] = ffma2(xv, wx, acc2[p][0]);
        acc2[p][1] = ffma2(xv, wy, acc2[p][1]);
        acc2[p][2] = ffma2(xv, wz, acc2[p][2]);
        acc2[p][3] = ffma2(xv, ww, acc2[p][3]);
      }
    }
  }
  __syncthreads();
  {
    float4 bb = *(const float4*)(b1s + tx*4);
    #pragma unroll
    for (int p = 0; p < 4; p++) {
      float a0, a1;
      float4 h0, h1;
      unpack2(acc2[p][0], a0, a1); h0.x = fmaxf(a0 + bb.x, 0.f); h1.x = fmaxf(a1 + bb.x, 0.f);
      unpack2(acc2[p][1], a0, a1); h0.y = fmaxf(a0 + bb.y, 0.f); h1.y = fmaxf(a1 + bb.y, 0.f);
      unpack2(acc2[p][2], a0, a1); h0.z = fmaxf(a0 + bb.z, 0.f); h1.z = fmaxf(a1 + bb.z, 0.f);
      unpack2(acc2[p][3], a0, a1); h0.w = fmaxf(a0 + bb.w, 0.f); h1.w = fmaxf(a1 + bb.w, 0.f);
      *(float4*)(hs + (wid*8 + 2*p    )*CC + tx*4) = h0;
      *(float4*)(hs + (wid*8 + 2*p + 1)*CC + tx*4) = h1;
    }
  }
  __syncthreads();

  // ---- stage 2: logits = (h @ W2 + b2) * scaling, f32x2 packed over K ----
  const float sc = scaling[0];
  {
    u64 a2[8];
    #pragma unroll
    for (int i = 0; i < 8; i++) a2[i] = 0ull;
    for (int j = 0; j < CC; j += 4) {
      u64 wA = pack2(W2s[(j+0)*KK + tx], W2s[(j+1)*KK + tx]);
      u64 wB = pack2(W2s[(j+2)*KK + tx], W2s[(j+3)*KK + tx]);
      #pragma unroll
      for (int i = 0; i < 8; i++) {
        ulonglong2 h2 = *(const ulonglong2*)(hs + (wid + 8*i)*CC + j);  // broadcast LDS.128
        a2[i] = ffma2(h2.x, wA, a2[i]);
        a2[i] = ffma2(h2.y, wB, a2[i]);
      }
    }
    float am = ams[tx];
    float bv = b2s[tx];
    #pragma unroll
    for (int i = 0; i < 8; i++) {
      float e, o;
      unpack2(a2[i], e, o);
      float v = ((e + o) + bv) * sc;
      if (am == 0.f) v = -1e9f;
      ls[(wid + 8*i)*33 + tx] = v;
    }
  }
  __syncthreads();

  // ---- stage 4a (moved up): stage x tile into hs (dead after stage 2) ----
  // issued BEFORE stage 3 so the L2 load latency hides under threefry/softmax ALU
  for (int idx = tid; idx < nvalid*32; idx += 256) {
    int r = idx >> 5, cq = idx & 31;
    *(float4*)(hs + r*128 + cq*4) = *(const float4*)(x + (size_t)(r0 + r)*CC + cq*4);
  }

  // ---- stage 3: gumbel + softmax + s (gmem AND smem) + reductions ----
  float a_avg = 0.f, a_px = 0.f, a_py = 0.f, a_q = 0.f, a_ent = 0.f;
  int cur_b = -1; float b_s = 0.f, b_px = 0.f, b_py = 0.f;
  for (int r = wid; r < nvalid; r += 8) {
    const int grow = r0 + r;
    float z = ls[r*33 + tx];
    z += gumbel_at((unsigned)grow * 32u + (unsigned)tx);   // TAU = 1
    float m = z;
    #pragma unroll
    for (int off = 16; off; off >>= 1) m = fmaxf(m, __shfl_xor_sync(0xffffffffu, m, off));
    float e = __expf(z - m);
    float ssum = e;
    #pragma unroll
    for (int off = 16; off; off >>= 1) ssum += __shfl_xor_sync(0xffffffffu, ssum, off);
    float s = e / ssum;
    out_s[(size_t)grow * KK + tx] = s;
    ls[r*33 + tx] = s;

    float px = pos[grow*2 + 0];
    float py = pos[grow*2 + 1];
    a_ent += s * __logf(s + EPSF);
    a_avg += s;
    a_px = fmaf(s, px, a_px);
    a_py = fmaf(s, py, a_py);
    a_q  = fmaf(s, px*px + py*py, a_q);

    int b = bsh[r];
    if (b != cur_b) {
      if (cur_b >= 0) {
        atomicAdd(&g_scr.sum_s[cur_b][tx], b_s);
        atomicAdd(&g_scr.sum_s_pos[cur_b][tx][0], b_px);
        atomicAdd(&g_scr.sum_s_pos[cur_b][tx][1], b_py);
      }
      cur_b = b; b_s = 0.f; b_px = 0.f; b_py = 0.f;
    }
    b_s += s; b_px = fmaf(s, px, b_px); b_py = fmaf(s, py, b_py);
  }
  if (cur_b >= 0) {
    atomicAdd(&g_scr.sum_s[cur_b][tx], b_s);
    atomicAdd(&g_scr.sum_s_pos[cur_b][tx][0], b_px);
    atomicAdd(&g_scr.sum_s_pos[cur_b][tx][1], b_py);
    atomicAdd(&g_scr.avg_sum[tx], a_avg);
    atomicAdd(&g_scr.stpos[tx][0], a_px);
    atomicAdd(&g_scr.stpos[tx][1], a_py);
    atomicAdd(&g_scr.stpossq[tx], a_q);
    #pragma unroll
    for (int off = 16; off; off >>= 1) a_ent += __shfl_xor_sync(0xffffffffu, a_ent, off);
    if (tx == 0) atomicAdd(&g_scr.ent_sum, a_ent);
  }
  __syncthreads();   // s in ls + x in hs both ready for all warps

  // ---- stage 4b (fused pooling): out[b] += S_tile^T X_tile, f32x2 over col pairs ----
  {
    int p = 0;
    while (p < nvalid) {           // uniform (shared bsh)
      const int b = bsh[p];
      int e = p + 1;
      while (e < nvalid && bsh[e] == b) e++;
      u64 pa2[4][2];
      #pragma unroll
      for (int ki = 0; ki < 4; ki++) { pa2[ki][0]=0ull; pa2[ki][1]=0ull; }
      for (int r = p; r < e; r++) {
        ulonglong2 x2 = *(const ulonglong2*)(hs + r*128 + tx*4);
        #pragma unroll
        for (int ki = 0; ki < 4; ki++) {
          u64 svp = dup2(ls[r*33 + wid + 8*ki]);   // warp-uniform broadcast
          pa2[ki][0] = ffma2(svp, x2.x, pa2[ki][0]);
          pa2[ki][1] = ffma2(svp, x2.y, pa2[ki][1]);
        }
      }
      float* ob = out_pool + (size_t)b * KK * CC;
      #pragma unroll
      for (int ki = 0; ki < 4; ki++) {
        float v0, v1, v2, v3;
        unpack2(pa2[ki][0], v0, v1);
        unpack2(pa2[ki][1], v2, v3);
        float* dst = ob + (size_t)(wid + 8*ki)*CC + tx*4;
        atomicAdd(dst+0, v0);
        atomicAdd(dst+1, v1);
        atomicAdd(dst+2, v2);
        atomicAdd(dst+3, v3);
      }
      p = e;
    }
  }
}

// ---------------- finisher: super_node_mu + 9 losses (parallelized) ----------------
__global__ void k_final(const float* __restrict__ amask, float* __restrict__ out)
{
  __shared__ float mu[BB*KK*2];
  __shared__ float wsum[16];
  __shared__ float s_sep;
  float* out_mu = out + (size_t)BB*KK*CC + (size_t)NN*KK;
  float* out_losses = out_mu + BB*KK*2;
  const int tid = threadIdx.x;  // 512 threads
  if (tid < BB*KK) {
    int b = tid >> 5, k = tid & 31;
    float ssv = g_scr.sum_s[b][k] + EPSF;
    float mx = g_scr.sum_s_pos[b][k][0] / ssv;
    float my = g_scr.sum_s_pos[b][k][1] / ssv;
    mu[tid*2+0] = mx; mu[tid*2+1] = my;
    out_mu[tid*2+0] = mx; out_mu[tid*2+1] = my;
  }
  __syncthreads();
  float rep = 0.f;
  for (int idx = tid; idx < BB*KK*KK; idx += 512) {
    int b = idx >> 10, k1 = (idx >> 5) & 31, k2 = idx & 31;
    if (k1 != k2) {
      float dx = mu[(b*32+k1)*2+0] - mu[(b*32+k2)*2+0];
      float dy = mu[(b*32+k1)*2+1] - mu[(b*32+k2)*2+1];
      rep += 1.f / (dx*dx + dy*dy + 1.f);
    }
  }
  #pragma unroll
  for (int off = 16; off; off >>= 1) rep += __shfl_xor_sync(0xffffffffu, rep, off);
  if ((tid & 31) == 0) wsum[tid >> 5] = rep;
  __syncthreads();
  if (tid == 0) {
    float sep = 0.f;
    for (int i = 0; i < 16; i++) sep += wsum[i];
    s_sep = sep / ((float)(KK*(KK-1)) + EPSF);
  }
  __syncthreads();

  if (tid < 32) {
    const int k = tid;
    const float Nf = (float)NN;
    const float u = 1.f/32.f;
    float avg = g_scr.avg_sum[k] / Nf;
    float amk = amask[k];
    float div_k  = avg * logf(avg + EPSF);
    float bal_k  = u * logf(u / (avg + EPSF));
    float prn_k  = fabsf(avg * (1.f - amk));
    float ssv = g_scr.avg_sum[k] + EPSF;
    float sx = g_scr.stpos[k][0] / ssv;
    float sy = g_scr.stpos[k][1] / ssv;
    float A  = g_scr.stpossq[k] / ssv;
    float musq = sx*sx + sy*sy;
    float spa_k = A - 2.f*musq + musq;

    float div = div_k, bal = bal_k, prn = prn_k, spa = spa_k, ams = amk, mean = avg, mx = avg;
    #pragma unroll
    for (int off = 16; off; off >>= 1) {
      div  += __shfl_xor_sync(0xffffffffu, div,  off);
      bal  += __shfl_xor_sync(0xffffffffu, bal,  off);
      prn  += __shfl_xor_sync(0xffffffffu, prn,  off);
      spa  += __shfl_xor_sync(0xffffffffu, spa,  off);
      ams  += __shfl_xor_sync(0xffffffffu, ams,  off);
      mean += __shfl_xor_sync(0xffffffffu, mean, off);
      mx    = fmaxf(mx, __shfl_xor_sync(0xffffffffu, mx, off));
    }
    mean /= 32.f;
    float d = avg - mean;
    float var = d*d;
    #pragma unroll
    for (int off = 16; off; off >>= 1) var += __shfl_xor_sync(0xffffffffu, var, off);
    var /= 31.f;

    if (k == 0) {
      float entropy = -g_scr.ent_sum / Nf;
      float maxp = fmaxf(mx - 0.8f, 0.f); maxp = maxp*maxp*10.f;
      float ent_avg = -div;
      float ep = fmaxf(0.5f * 3.4657359027997265f - ent_avg, 0.f); ep = ep*ep;
      float collapse = (var + maxp + ep) * 2.0f;
      out_losses[0] = entropy;
      out_losses[1] = div;
      out_losses[2] = spa / 32.f;
      out_losses[3] = prn / 32.f;
      out_losses[4] = ams / 32.f * 0.01f;
      out_losses[5] = 0.f;
      out_losses[6] = collapse;
      out_losses[7] = bal;
      out_losses[8] = s_sep;
    }
  }
}

// ---------------- launch ----------------
extern "C" void kernel_launch(void* const* d_in, const int* in_sizes, int n_in,
                              void* d_out, int out_size) {
  const float* x       = (const float*)d_in[0];
  const float* pos     = (const float*)d_in[1];
  const float* W1      = (const float*)d_in[2];
  const float* b1      = (const float*)d_in[3];
  const float* W2      = (const float*)d_in[4];
  const float* b2      = (const float*)d_in[5];
  const float* scaling = (const float*)d_in[6];
  const float* amask   = (const float*)d_in[7];
  const int*   batch   = (const int*)d_in[8];
  float* out   = (float*)d_out;
  float* out_s = out + BB*KK*CC;

  cudaFuncSetAttribute(k_assign, cudaFuncAttributeMaxDynamicSharedMemorySize, SM_TOTAL_F*4);

  k_zero<<<(BB*KK*CC/4 + 255)/256, 256>>>(out);
  k_assign<<<(NN + 63)/64, 256, SM_TOTAL_F*4>>>(x, pos, W1, b1, W2, b2, scaling, amask, batch, out_s, out);
  k_final<<<1, 512>>>(amask, out);
}

// round 10
// speedup vs baseline: 1.3376x; 1.0087x over previous
#include <cuda_runtime.h>
#include <math.h>
#include <stdint.h>

#define NN 50000
#define CC 128
#define KK 32
#define BB 16
#define EPSF 1e-9f
#define TINYF 1.17549435e-38f

typedef unsigned long long u64;

// ---------------- f32x2 packed math (Blackwell, PTX-only) ----------------
__device__ __forceinline__ u64 pack2(float lo, float hi) {
  u64 r; asm("mov.b64 %0, {%1, %2};" : "=l"(r) : "f"(lo), "f"(hi)); return r;
}
__device__ __forceinline__ u64 dup2(float v) { return pack2(v, v); }
__device__ __forceinline__ void unpack2(u64 p, float& lo, float& hi) {
  asm("mov.b64 {%0, %1}, %2;" : "=f"(lo), "=f"(hi) : "l"(p));
}
__device__ __forceinline__ u64 ffma2(u64 a, u64 b, u64 c) {
  u64 d; asm("fma.rn.f32x2 %0, %1, %2, %3;" : "=l"(d) : "l"(a), "l"(b), "l"(c)); return d;
}
__device__ __forceinline__ void cp_async16(uint32_t smem, const void* gptr) {
  asm volatile("cp.async.cg.shared.global [%0], [%1], 16;" :: "r"(smem), "l"(gptr) : "memory");
}

// ---------------- scratch (device globals: allocation-free) ----------------
struct Scratch {
  float avg_sum[KK];
  float stpos[KK][2];
  float stpossq[KK];
  float sum_s[BB][KK];
  float sum_s_pos[BB][KK][2];
  float ent_sum;
};
__device__ Scratch g_scr;
#define SCR_FLOATS 1665

__global__ void k_zero(float* __restrict__ out) {
  int i = blockIdx.x * 256 + threadIdx.x;
  float4 z = make_float4(0.f, 0.f, 0.f, 0.f);
  if (i < (BB*KK*CC)/4) ((float4*)out)[i] = z;
  if (i < SCR_FLOATS) ((float*)&g_scr)[i] = 0.f;
}

// ---------------- JAX threefry2x32 (bit-exact) ----------------
__device__ __forceinline__ void tf_round(unsigned &x0, unsigned &x1, int r) {
  x0 += x1;
  x1 = __funnelshift_l(x1, x1, r);
  x1 ^= x0;
}
__device__ __forceinline__ uint2 threefry(unsigned k0, unsigned k1, unsigned x0, unsigned x1) {
  unsigned k2 = k0 ^ k1 ^ 0x1BD11BDAu;
  x0 += k0; x1 += k1;
  tf_round(x0,x1,13); tf_round(x0,x1,15); tf_round(x0,x1,26); tf_round(x0,x1,6);
  x0 += k1; x1 += k2 + 1u;
  tf_round(x0,x1,17); tf_round(x0,x1,29); tf_round(x0,x1,16); tf_round(x0,x1,24);
  x0 += k2; x1 += k0 + 2u;
  tf_round(x0,x1,13); tf_round(x0,x1,15); tf_round(x0,x1,26); tf_round(x0,x1,6);
  x0 += k0; x1 += k1 + 3u;
  tf_round(x0,x1,17); tf_round(x0,x1,29); tf_round(x0,x1,16); tf_round(x0,x1,24);
  x0 += k1; x1 += k2 + 4u;
  tf_round(x0,x1,13); tf_round(x0,x1,15); tf_round(x0,x1,26); tf_round(x0,x1,6);
  x0 += k2; x1 += k0 + 5u;
  return make_uint2(x0, x1);
}

// Partitionable counter-mode (verified R3): bits(i) = o.x ^ o.y
__device__ __forceinline__ float gumbel_at(unsigned idx) {
  uint2 o = threefry(0u, 42u, 0u, idx);
  unsigned bits = o.x ^ o.y;
  float u = __uint_as_float((bits >> 9) | 0x3f800000u) - 1.0f;
  u = fmaxf(TINYF, u + TINYF);
  return -__logf(-__logf(u));
}

// ---------------- fused assign+pool kernel ----------------
// smem layout (floats):
#define XS_STRIDE 66              // even stride: row-pairs are 8B-aligned for LDS.64
#define SM_W2  0                  // 4096
#define SM_B1  4096               // 128
#define SM_B2  (4096+128)         // 32
#define SM_AM  (4096+160)         // 32
#define SM_UNI (4096+192)         // union: 10304 (stage1: xs[32*66]+w1s[2][32*128]; stage2/pool: hs[64*128])
#define SM_LS  (SM_UNI+10304)     // 64*33 = 2112 (logits, then s)
#define SM_BSH (SM_LS+2112)       // 64 ints
#define SM_TOTAL_F (SM_BSH+64)    // 16768 floats = 67072 B  (x3 CTAs = 201 KB)

__global__ void __launch_bounds__(256, 3)
k_assign(const float* __restrict__ x, const float* __restrict__ pos,
         const float* __restrict__ W1, const float* __restrict__ b1,
         const float* __restrict__ W2, const float* __restrict__ b2,
         const float* __restrict__ scaling, const float* __restrict__ amask,
         const int* __restrict__ batch, float* __restrict__ out_s,
         float* __restrict__ out_pool)
{
  extern __shared__ float sm[];
  float* W2s = sm + SM_W2;
  float* b1s = sm + SM_B1;
  float* b2s = sm + SM_B2;
  float* ams = sm + SM_AM;
  float* uni = sm + SM_UNI;
  float* xs  = uni;               // [32][66]
  float* w1s = uni + 32*XS_STRIDE;// [2][32][128] double buffer
  float* hs  = uni;               // [64][128] (aliases stage-1 tiles; pool: x tile)
  float* ls  = sm + SM_LS;        // [64][33]
  int*   bsh = (int*)(sm + SM_BSH);

  const int tid = threadIdx.x;
  const int tx  = tid & 31;
  const int wid = tid >> 5;
  const int r0  = blockIdx.x * 64;
  const int nvalid = min(64, NN - r0);
  const uint32_t w1s_sm = (uint32_t)__cvta_generic_to_shared(w1s);

  for (int i = tid; i < CC*KK; i += 256) W2s[i] = W2[i];
  if (tid < 128) b1s[tid] = b1[tid];
  if (tid < 32)  { b2s[tid] = b2[tid]; ams[tid] = amask[tid]; }
  if (tid < 64)  bsh[tid] = (tid < nvalid) ? batch[r0 + tid] : 0;

  // ---- stage 1: h = relu(x @ W1 + b1), pipelined tiles ----
  u64 acc2[4][4];
  #pragma unroll
  for (int p = 0; p < 4; p++) { acc2[p][0]=0ull; acc2[p][1]=0ull; acc2[p][2]=0ull; acc2[p][3]=0ull; }

  // prologue: x tile 0 -> regs, W1 tile 0 -> smem buf0 via cp.async
  float xreg[8];
  #pragma unroll
  for (int rr = 0; rr < 8; rr++) {
    int r = wid + rr*8;
    xreg[rr] = (r < nvalid) ? x[(size_t)(r0 + r)*CC + tx] : 0.f;
  }
  #pragma unroll
  for (int kk2 = 0; kk2 < 4; kk2++) {
    int k = wid + kk2*8;
    cp_async16(w1s_sm + (uint32_t)(k*CC + tx*4)*4u, W1 + (size_t)k*CC + tx*4);
  }
  asm volatile("cp.async.commit_group;" ::: "memory");

  int buf = 0;
  for (int it = 0; it < 4; it++) {
    const int c0 = it*32;
    // commit x regs (tile it) to xs
    #pragma unroll
    for (int rr = 0; rr < 8; rr++) xs[tx*XS_STRIDE + wid + rr*8] = xreg[rr];
    // prefetch x tile it+1 into regs (lands during compute below)
    if (it < 3) {
      #pragma unroll
      for (int rr = 0; rr < 8; rr++) {
        int r = wid + rr*8;
        xreg[rr] = (r < nvalid) ? x[(size_t)(r0 + r)*CC + c0 + 32 + tx] : 0.f;
      }
    }
    asm volatile("cp.async.wait_group 0;" ::: "memory");   // W1 tile it arrived
    __syncthreads();
    // prefetch W1 tile it+1 into the other buffer
    if (it < 3) {
      uint32_t db = w1s_sm + (uint32_t)((buf^1)*4096)*4u;
      #pragma unroll
      for (int kk2 = 0; kk2 < 4; kk2++) {
        int k = wid + kk2*8;
        cp_async16(db + (uint32_t)(k*CC + tx*4)*4u, W1 + (size_t)(c0 + 32 + k)*CC + tx*4);
      }
      asm volatile("cp.async.commit_group;" ::: "memory");
    }
    const float* w1b = w1s + buf*4096;
    #pragma unroll
    for (int kc = 0; kc < 32; kc++) {
      float4 w = *(const float4*)(w1b + kc*CC + tx*4);
      u64 wx = dup2(w.x), wy = dup2(w.y), wz = dup2(w.z), ww = dup2(w.w);
      const u64* xp = (const u64*)(xs + kc*XS_STRIDE + wid*8);  // warp-uniform LDS.64
      #pragma unroll
      for (int p = 0; p < 4; p++) {
        u64 xv = xp[p];          // rows (wid*8+2p, wid*8+2p+1)
        acc2[p][0] = ffma2(xv, wx, acc2[p][0]);
        acc2[p][1] = ffma2(xv, wy, acc2[p][1]);
        acc2[p][2] = ffma2(xv, wz, acc2[p][2]);
        acc2[p][3] = ffma2(xv, ww, acc2[p][3]);
      }
    }
    __syncthreads();   // xs consumed; safe to overwrite next iter
    buf ^= 1;
  }
  {
    float4 bb = *(const float4*)(b1s + tx*4);
    #pragma unroll
    for (int p = 0; p < 4; p++) {
      float a0, a1;
      float4 h0, h1;
      unpack2(acc2[p][0], a0, a1); h0.x = fmaxf(a0 + bb.x, 0.f); h1.x = fmaxf(a1 + bb.x, 0.f);
      unpack2(acc2[p][1], a0, a1); h0.y = fmaxf(a0 + bb.y, 0.f); h1.y = fmaxf(a1 + bb.y, 0.f);
      unpack2(acc2[p][2], a0, a1); h0.z = fmaxf(a0 + bb.z, 0.f); h1.z = fmaxf(a1 + bb.z, 0.f);
      unpack2(acc2[p][3], a0, a1); h0.w = fmaxf(a0 + bb.w, 0.f); h1.w = fmaxf(a1 + bb.w, 0.f);
      *(float4*)(hs + (wid*8 + 2*p    )*CC + tx*4) = h0;
      *(float4*)(hs + (wid*8 + 2*p + 1)*CC + tx*4) = h1;
    }
  }
  __syncthreads();

  // ---- stage 2: logits = (h @ W2 + b2) * scaling, f32x2 packed over K ----
  const float sc = scaling[0];
  {
    u64 a2[8];
    #pragma unroll
    for (int i = 0; i < 8; i++) a2[i] = 0ull;
    for (int j = 0; j < CC; j += 4) {
      u64 wA = pack2(W2s[(j+0)*KK + tx], W2s[(j+1)*KK + tx]);
      u64 wB = pack2(W2s[(j+2)*KK + tx], W2s[(j+3)*KK + tx]);
      #pragma unroll
      for (int i = 0; i < 8; i++) {
        ulonglong2 h2 = *(const ulonglong2*)(hs + (wid + 8*i)*CC + j);  // broadcast LDS.128
        a2[i] = ffma2(h2.x, wA, a2[i]);
        a2[i] = ffma2(h2.y, wB, a2[i]);
      }
    }
    float am = ams[tx];
    float bv = b2s[tx];
    #pragma unroll
    for (int i = 0; i < 8; i++) {
      float e, o;
      unpack2(a2[i], e, o);
      float v = ((e + o) + bv) * sc;
      if (am == 0.f) v = -1e9f;
      ls[(wid + 8*i)*33 + tx] = v;
    }
  }
  __syncthreads();

  // ---- stage 4a: stage x tile into hs (dead after stage 2); latency hides under stage 3 ----
  for (int idx = tid; idx < nvalid*32; idx += 256) {
    int r = idx >> 5, cq = idx & 31;
    *(float4*)(hs + r*128 + cq*4) = *(const float4*)(x + (size_t)(r0 + r)*CC + cq*4);
  }

  // ---- stage 3: gumbel + softmax + s (gmem AND smem) + reductions ----
  float a_avg = 0.f, a_px = 0.f, a_py = 0.f, a_q = 0.f, a_ent = 0.f;
  int cur_b = -1; float b_s = 0.f, b_px = 0.f, b_py = 0.f;
  for (int r = wid; r < nvalid; r += 8) {
    const int grow = r0 + r;
    float z = ls[r*33 + tx];
    z += gumbel_at((unsigned)grow * 32u + (unsigned)tx);   // TAU = 1
    float m = z;
    #pragma unroll
    for (int off = 16; off; off >>= 1) m = fmaxf(m, __shfl_xor_sync(0xffffffffu, m, off));
    float e = __expf(z - m);
    float ssum = e;
    #pragma unroll
    for (int off = 16; off; off >>= 1) ssum += __shfl_xor_sync(0xffffffffu, ssum, off);
    float s = e / ssum;
    out_s[(size_t)grow * KK + tx] = s;
    ls[r*33 + tx] = s;

    float px = pos[grow*2 + 0];
    float py = pos[grow*2 + 1];
    a_ent += s * __logf(s + EPSF);
    a_avg += s;
    a_px = fmaf(s, px, a_px);
    a_py = fmaf(s, py, a_py);
    a_q  = fmaf(s, px*px + py*py, a_q);

    int b = bsh[r];
    if (b != cur_b) {
      if (cur_b >= 0) {
        atomicAdd(&g_scr.sum_s[cur_b][tx], b_s);
        atomicAdd(&g_scr.sum_s_pos[cur_b][tx][0], b_px);
        atomicAdd(&g_scr.sum_s_pos[cur_b][tx][1], b_py);
      }
      cur_b = b; b_s = 0.f; b_px = 0.f; b_py = 0.f;
    }
    b_s += s; b_px = fmaf(s, px, b_px); b_py = fmaf(s, py, b_py);
  }
  if (cur_b >= 0) {
    atomicAdd(&g_scr.sum_s[cur_b][tx], b_s);
    atomicAdd(&g_scr.sum_s_pos[cur_b][tx][0], b_px);
    atomicAdd(&g_scr.sum_s_pos[cur_b][tx][1], b_py);
    atomicAdd(&g_scr.avg_sum[tx], a_avg);
    atomicAdd(&g_scr.stpos[tx][0], a_px);
    atomicAdd(&g_scr.stpos[tx][1], a_py);
    atomicAdd(&g_scr.stpossq[tx], a_q);
    #pragma unroll
    for (int off = 16; off; off >>= 1) a_ent += __shfl_xor_sync(0xffffffffu, a_ent, off);
    if (tx == 0) atomicAdd(&g_scr.ent_sum, a_ent);
  }
  __syncthreads();   // s in ls + x in hs both ready for all warps

  // ---- stage 4b (fused pooling): out[b] += S_tile^T X_tile, f32x2 over col pairs ----
  {
    int p = 0;
    while (p < nvalid) {           // uniform (shared bsh)
      const int b = bsh[p];
      int e = p + 1;
      while (e < nvalid && bsh[e] == b) e++;
      u64 pa2[4][2];
      #pragma unroll
      for (int ki = 0; ki < 4; ki++) { pa2[ki][0]=0ull; pa2[ki][1]=0ull; }
      for (int r = p; r < e; r++) {
        ulonglong2 x2 = *(const ulonglong2*)(hs + r*128 + tx*4);
        #pragma unroll
        for (int ki = 0; ki < 4; ki++) {
          u64 svp = dup2(ls[r*33 + wid + 8*ki]);   // warp-uniform broadcast
          pa2[ki][0] = ffma2(svp, x2.x, pa2[ki][0]);
          pa2[ki][1] = ffma2(svp, x2.y, pa2[ki][1]);
        }
      }
      float* ob = out_pool + (size_t)b * KK * CC;
      #pragma unroll
      for (int ki = 0; ki < 4; ki++) {
        float v0, v1, v2, v3;
        unpack2(pa2[ki][0], v0, v1);
        unpack2(pa2[ki][1], v2, v3);
        float* dst = ob + (size_t)(wid + 8*ki)*CC + tx*4;
        atomicAdd(dst+0, v0);
        atomicAdd(dst+1, v1);
        atomicAdd(dst+2, v2);
        atomicAdd(dst+3, v3);
      }
      p = e;
    }
  }
}

// ---------------- finisher: super_node_mu + 9 losses (parallelized) ----------------
__global__ void k_final(const float* __restrict__ amask, float* __restrict__ out)
{
  __shared__ float mu[BB*KK*2];
  __shared__ float wsum[16];
  __shared__ float s_sep;
  float* out_mu = out + (size_t)BB*KK*CC + (size_t)NN*KK;
  float* out_losses = out_mu + BB*KK*2;
  const int tid = threadIdx.x;  // 512 threads
  if (tid < BB*KK) {
    int b = tid >> 5, k = tid & 31;
    float ssv = g_scr.sum_s[b][k] + EPSF;
    float mx = g_scr.sum_s_pos[b][k][0] / ssv;
    float my = g_scr.sum_s_pos[b][k][1] / ssv;
    mu[tid*2+0] = mx; mu[tid*2+1] = my;
    out_mu[tid*2+0] = mx; out_mu[tid*2+1] = my;
  }
  __syncthreads();
  float rep = 0.f;
  for (int idx = tid; idx < BB*KK*KK; idx += 512) {
    int b = idx >> 10, k1 = (idx >> 5) & 31, k2 = idx & 31;
    if (k1 != k2) {
      float dx = mu[(b*32+k1)*2+0] - mu[(b*32+k2)*2+0];
      float dy = mu[(b*32+k1)*2+1] - mu[(b*32+k2)*2+1];
      rep += 1.f / (dx*dx + dy*dy + 1.f);
    }
  }
  #pragma unroll
  for (int off = 16; off; off >>= 1) rep += __shfl_xor_sync(0xffffffffu, rep, off);
  if ((tid & 31) == 0) wsum[tid >> 5] = rep;
  __syncthreads();
  if (tid == 0) {
    float sep = 0.f;
    for (int i = 0; i < 16; i++) sep += wsum[i];
    s_sep = sep / ((float)(KK*(KK-1)) + EPSF);
  }
  __syncthreads();

  if (tid < 32) {
    const int k = tid;
    const float Nf = (float)NN;
    const float u = 1.f/32.f;
    float avg = g_scr.avg_sum[k] / Nf;
    float amk = amask[k];
    float div_k  = avg * logf(avg + EPSF);
    float bal_k  = u * logf(u / (avg + EPSF));
    float prn_k  = fabsf(avg * (1.f - amk));
    float ssv = g_scr.avg_sum[k] + EPSF;
    float sx = g_scr.stpos[k][0] / ssv;
    float sy = g_scr.stpos[k][1] / ssv;
    float A  = g_scr.stpossq[k] / ssv;
    float musq = sx*sx + sy*sy;
    float spa_k = A - 2.f*musq + musq;

    float div = div_k, bal = bal_k, prn = prn_k, spa = spa_k, ams = amk, mean = avg, mx = avg;
    #pragma unroll
    for (int off = 16; off; off >>= 1) {
      div  += __shfl_xor_sync(0xffffffffu, div,  off);
      bal  += __shfl_xor_sync(0xffffffffu, bal,  off);
      prn  += __shfl_xor_sync(0xffffffffu, prn,  off);
      spa  += __shfl_xor_sync(0xffffffffu, spa,  off);
      ams  += __shfl_xor_sync(0xffffffffu, ams,  off);
      mean += __shfl_xor_sync(0xffffffffu, mean, off);
      mx    = fmaxf(mx, __shfl_xor_sync(0xffffffffu, mx, off));
    }
    mean /= 32.f;
    float d = avg - mean;
    float var = d*d;
    #pragma unroll
    for (int off = 16; off; off >>= 1) var += __shfl_xor_sync(0xffffffffu, var, off);
    var /= 31.f;

    if (k == 0) {
      float entropy = -g_scr.ent_sum / Nf;
      float maxp = fmaxf(mx - 0.8f, 0.f); maxp = maxp*maxp*10.f;
      float ent_avg = -div;
      float ep = fmaxf(0.5f * 3.4657359027997265f - ent_avg, 0.f); ep = ep*ep;
      float collapse = (var + maxp + ep) * 2.0f;
      out_losses[0] = entropy;
      out_losses[1] = div;
      out_losses[2] = spa / 32.f;
      out_losses[3] = prn / 32.f;
      out_losses[4] = ams / 32.f * 0.01f;
      out_losses[5] = 0.f;
      out_losses[6] = collapse;
      out_losses[7] = bal;
      out_losses[8] = s_sep;
    }
  }
}

// ---------------- launch ----------------
extern "C" void kernel_launch(void* const* d_in, const int* in_sizes, int n_in,
                              void* d_out, int out_size) {
  const float* x       = (const float*)d_in[0];
  const float* pos     = (const float*)d_in[1];
  const float* W1      = (const float*)d_in[2];
  const float* b1      = (const float*)d_in[3];
  const float* W2      = (const float*)d_in[4];
  const float* b2      = (const float*)d_in[5];
  const float* scaling = (const float*)d_in[6];
  const float* amask   = (const float*)d_in[7];
  const int*   batch   = (const int*)d_in[8];
  float* out   = (float*)d_out;
  float* out_s = out + BB*KK*CC;

  cudaFuncSetAttribute(k_assign, cudaFuncAttributeMaxDynamicSharedMemorySize, SM_TOTAL_F*4);

  k_zero<<<(BB*KK*CC/4 + 255)/256, 256>>>(out);
  k_assign<<<(NN + 63)/64, 256, SM_TOTAL_F*4>>>(x, pos, W1, b1, W2, b2, scaling, amask, batch, out_s, out);
  k_final<<<1, 512>>>(amask, out);
}